// round 17
// baseline (speedup 1.0000x reference)
#include <cuda_runtime.h>

// Chamfer distance via exact grid NN search, v5.
// GRID=64 (cell 0.25): ~3x smaller per-warp candidate union than GRID=32.
// u64 z-masks per column; prefix1 writes packed cells directly (no cellpack).
// Query = proven v3 scan (simple loop) + fused ticket finalize. 6 launches.

#define BB 8
#define NN 8192
#define GRID 64
#define NC (GRID * GRID * GRID)        // 262144 cells per segment
#define NSEG 16                        // 2 target-sets x 8 batches
#define NPTS (2 * BB * NN)             // 131072
#define CS 0.25f
#define LO (-8.0f)
#define INVCS 4.0f
#define EPS 1e-5f
#define NBLK (NC / 1024)               // 256 prefix blocks per segment
#define QT 256
#define QBLOCKS (NPTS / QT)            // 512
#define FXS 4398046511104.0            // 2^42 fixed-point scale

__device__ unsigned g_cnt[NSEG][NC];
__device__ unsigned g_off[NSEG][NC];             // scatter cursors
__device__ unsigned g_bsum[NSEG][NBLK];
__device__ unsigned g_bsumx[NSEG][NBLK];
__device__ unsigned g_cell[NSEG][NC];            // local_excl<<14 | cnt
__device__ unsigned long long g_mask[NSEG][GRID * GRID];  // z-occupancy
__device__ float4   g_pts[NSEG][NN];             // cell-sorted (x,y,z,|p|^2)
__device__ unsigned long long g_isum;
__device__ unsigned g_done;                       // zero-init; self-resetting

__device__ __forceinline__ int cell_coord(float v) {
    int c = (int)floorf((v - LO) * INVCS);
    return min(GRID - 1, max(0, c));
}
__device__ __forceinline__ float axis_dist(float q, int i) {
    float lo = LO + i * CS;
    return fmaxf(0.0f, fmaxf(lo - q, q - (lo + CS)));
}

// ---- K0: zero counts, masks, accumulator ----
#define ZELEMS (NSEG * NC + NSEG * GRID * GRID * 2)
__global__ void knn_zero() {
    unsigned idx = blockIdx.x * 1024u + threadIdx.x;
    if (idx < NSEG * NC) ((unsigned*)g_cnt)[idx] = 0u;
    else if (idx < ZELEMS) ((unsigned*)g_mask)[idx - NSEG * NC] = 0u;
    if (idx == 0) g_isum = 0ull;
}

// ---- K1: count + column masks ----
__global__ __launch_bounds__(256)
void knn_count(const float* __restrict__ pred, const float* __restrict__ gt) {
    int idx = blockIdx.x * 256 + threadIdx.x;
    int t = idx >> 16, b = (idx >> 13) & 7, i = idx & 8191;
    const float* p = (t == 0 ? gt : pred) + ((long)(b * NN + i)) * 3;
    int ix = cell_coord(p[0]), iy = cell_coord(p[1]), iz = cell_coord(p[2]);
    int seg = t * 8 + b;
    atomicAdd(&g_cnt[seg][((ix << 6) | iy) << 6 | iz], 1u);
    atomicOr(&g_mask[seg][(ix << 6) | iy], 1ull << iz);
}

// ---- K2: per-1024-cell-block excl prefix; writes cursors + packed cells ----
__global__ __launch_bounds__(256)
void knn_prefix1() {
    const int seg = blockIdx.y, blk = blockIdx.x, tid = threadIdx.x;
    const int base = blk * 1024 + tid * 4;
    unsigned c0 = g_cnt[seg][base], c1 = g_cnt[seg][base + 1];
    unsigned c2 = g_cnt[seg][base + 2], c3 = g_cnt[seg][base + 3];
    unsigned e1 = c0, e2 = c0 + c1, e3 = e2 + c2;
    unsigned tsum = e3 + c3;
    __shared__ unsigned s[256];
    s[tid] = tsum;
    __syncthreads();
    for (int o = 1; o < 256; o <<= 1) {
        unsigned v = (tid >= o) ? s[tid - o] : 0u;
        __syncthreads();
        s[tid] += v;
        __syncthreads();
    }
    unsigned excl = s[tid] - tsum;
    g_off[seg][base]     = excl;
    g_off[seg][base + 1] = excl + e1;
    g_off[seg][base + 2] = excl + e2;
    g_off[seg][base + 3] = excl + e3;
    g_cell[seg][base]     = (excl << 14) | c0;
    g_cell[seg][base + 1] = ((excl + e1) << 14) | c1;
    g_cell[seg][base + 2] = ((excl + e2) << 14) | c2;
    g_cell[seg][base + 3] = ((excl + e3) << 14) | c3;
    if (tid == 0) g_bsum[seg][blk] = s[255];
}

// ---- K3: scan 256 block totals per segment ----
__global__ __launch_bounds__(256)
void knn_prefix2() {
    const int seg = blockIdx.x, tid = threadIdx.x;
    unsigned v = g_bsum[seg][tid];
    __shared__ unsigned s[256];
    s[tid] = v;
    __syncthreads();
    for (int o = 1; o < 256; o <<= 1) {
        unsigned u = (tid >= o) ? s[tid - o] : 0u;
        __syncthreads();
        s[tid] += u;
        __syncthreads();
    }
    g_bsumx[seg][tid] = s[tid] - v;
}

// ---- K4: scatter points into cell order ----
__global__ __launch_bounds__(256)
void knn_scatter(const float* __restrict__ pred, const float* __restrict__ gt) {
    int idx = blockIdx.x * 256 + threadIdx.x;
    int t = idx >> 16, b = (idx >> 13) & 7, i = idx & 8191;
    int seg = t * 8 + b;
    const float* p = (t == 0 ? gt : pred) + ((long)(b * NN + i)) * 3;
    float x = p[0], y = p[1], z = p[2];
    int ix = cell_coord(x), iy = cell_coord(y), iz = cell_coord(z);
    int c = ((ix << 6) | iy) << 6 | iz;
    unsigned local = atomicAdd(&g_off[seg][c], 1u);
    g_pts[seg][local + g_bsumx[seg][c >> 10]] =
        make_float4(x, y, z, x * x + y * y + z * z);
}

// Simple candidate scan (NO unroll — proven best in R15/R16 A/B).
__device__ __forceinline__ void scan_cell(int tseg, int c, float qx, float qy,
                                          float qz, float qw, float& best) {
    unsigned pc = g_cell[tseg][c];
    unsigned cn = pc & 16383u;
    if (!cn) return;
    unsigned st = (pc >> 14) + g_bsumx[tseg][c >> 10];
    for (unsigned s = st; s < st + cn; s++) {
        float4 p = g_pts[tseg][s];
        float d = (qw + p.w) - 2.0f * (qx * p.x + qy * p.y + qz * p.z);
        best = fminf(best, d);
    }
}

// ---- K5: exact ring search + fused finalize ----
__global__ __launch_bounds__(QT)
void knn_query(float* __restrict__ out) {
    int idx = blockIdx.x * QT + threadIdx.x;
    int qseg = idx >> 13, i = idx & 8191;
    int tseg = qseg ^ 8;
    float4 q = g_pts[qseg][i];
    float qx = q.x, qy = q.y, qz = q.z, qw = q.w;
    int ix = cell_coord(qx), iy = cell_coord(qy), iz = cell_coord(qz);

    float best = __int_as_float(0x7F800000);

    for (int r = 0; r < GRID; r++) {
        if (r >= 1) {
            float rb = (r - 1) * CS;
            if (rb * rb > best + EPS) break;
        }
        for (int dx = -r; dx <= r; dx++) {
            int xx = ix + dx;
            if ((unsigned)xx >= (unsigned)GRID) continue;
            float ax = axis_dist(qx, xx);
            float ax2 = ax * ax;
            if (ax2 > best + EPS) continue;
            bool xf = (dx == r) || (dx == -r);
            for (int dy = -r; dy <= r; dy++) {
                int yy = iy + dy;
                if ((unsigned)yy >= (unsigned)GRID) continue;
                float ay = axis_dist(qy, yy);
                float rxy = ax2 + ay * ay;
                if (rxy > best + EPS) continue;
                unsigned long long mask = g_mask[tseg][(xx << 6) | yy];
                if (!mask) continue;
                int cbase = (((xx << 6) | yy) << 6);
                if (xf || dy == r || dy == -r) {
                    int zlo = max(0, iz - r), zhi = min(GRID - 1, iz + r);
                    unsigned long long m = mask & (~0ull << zlo)
                                                & (~0ull >> (63 - zhi));
                    while (m) {
                        int zz = __ffsll(m) - 1;
                        m &= m - 1;
                        float az = axis_dist(qz, zz);
                        if (rxy + az * az > best + EPS) continue;
                        scan_cell(tseg, cbase | zz, qx, qy, qz, qw, best);
                    }
                } else {
                    int zz = iz - r;
                    if (zz >= 0 && ((mask >> zz) & 1ull)) {
                        float az = axis_dist(qz, zz);
                        if (rxy + az * az <= best + EPS)
                            scan_cell(tseg, cbase | zz, qx, qy, qz, qw, best);
                    }
                    zz = iz + r;
                    if (zz < GRID && ((mask >> zz) & 1ull)) {
                        float az = axis_dist(qz, zz);
                        if (rxy + az * az <= best + EPS)
                            scan_cell(tseg, cbase | zz, qx, qy, qz, qw, best);
                    }
                }
            }
        }
    }

    // Order-independent fixed-point sum -> deterministic output.
    unsigned long long fx = (unsigned long long)((double)best * FXS + 0.5);
    __shared__ unsigned long long ss[QT];
    ss[threadIdx.x] = fx;
    __syncthreads();
    for (int st = QT / 2; st > 0; st >>= 1) {
        if (threadIdx.x < st) ss[threadIdx.x] += ss[threadIdx.x + st];
        __syncthreads();
    }
    if (threadIdx.x == 0) {
        atomicAdd(&g_isum, ss[0]);
        __threadfence();
        unsigned ticket = atomicAdd(&g_done, 1u);
        if (ticket == QBLOCKS - 1) {
            unsigned long long total = atomicAdd(&g_isum, 0ull);
            atomicExch(&g_done, 0u);               // reset for next replay
            out[0] = (float)((double)total / FXS / (double)(BB * NN));
        }
    }
}

extern "C" void kernel_launch(void* const* d_in, const int* in_sizes, int n_in,
                              void* d_out, int out_size) {
    const float* pred = (const float*)d_in[0];
    const float* gt   = (const float*)d_in[1];
    float* out = (float*)d_out;

    knn_zero<<<(ZELEMS + 1023) / 1024, 1024>>>();
    knn_count<<<NPTS / 256, 256>>>(pred, gt);
    knn_prefix1<<<dim3(NBLK, NSEG), 256>>>();
    knn_prefix2<<<NSEG, 256>>>();
    knn_scatter<<<NPTS / 256, 256>>>(pred, gt);
    knn_query<<<QBLOCKS, QT>>>(out);
}